// round 12
// baseline (speedup 1.0000x reference)
#include <cuda_runtime.h>
#include <cuda_bf16.h>
#include <mma.h>
#include <cstdint>

#define B_SZ 2048
#define N_SZ 128
#define D_SZ 512
#define NT_F 128
#define GRID_F 592     // 4 CTAs/SM * 148 SMs, persistent

using namespace nvcuda;

// scratch: cw = content @ cow (fp32), plus bf16 split cow
__device__ float g_cw[B_SZ * 2 * D_SZ];                      // 8 MB
__device__ __nv_bfloat16 g_b_hi[D_SZ * D_SZ];                // 0.5 MB (cow, [k][n])
__device__ __nv_bfloat16 g_b_lo[D_SZ * D_SZ];                // 0.5 MB
__device__ int g_ctr;                                        // work-steal counter

__device__ __forceinline__ float tanh_mufu(float x) {
    float y; asm("tanh.approx.f32 %0, %1;" : "=f"(y) : "f"(x)); return y;
}
__device__ __forceinline__ float tanh_precise(float x) {
    float ax = fabsf(x);
    if (ax > 15.0f) return copysignf(1.0f, x);
    float t = __expf(2.0f * x);
    return (t - 1.0f) / (t + 1.0f);
}
__device__ __forceinline__ float warp_sum(float v) {
    #pragma unroll
    for (int o = 16; o > 0; o >>= 1) v += __shfl_xor_sync(0xffffffffu, v, o);
    return v;
}
__device__ __forceinline__ uint32_t smem_u32(const void* p) {
    uint32_t a;
    asm("{ .reg .u64 t; cvta.to.shared.u64 t, %1; cvt.u32.u64 %0, t; }" : "=r"(a) : "l"(p));
    return a;
}
__device__ __forceinline__ void cp_async16(uint32_t dst, const void* src, int src_bytes) {
    asm volatile("cp.async.cg.shared.global [%0], [%1], 16, %2;"
                 :: "r"(dst), "l"(src), "r"(src_bytes) : "memory");
}
#define CP_COMMIT() asm volatile("cp.async.commit_group;" ::: "memory")
#define CP_WAIT1()  asm volatile("cp.async.wait_group 1;" ::: "memory")
#define CP_WAIT0()  asm volatile("cp.async.wait_group 0;" ::: "memory")

// ======================= prep: cow split (+ counter reset) =================
__global__ void __launch_bounds__(256) prep_cow_kernel(const float* __restrict__ cow)
{
    if (blockIdx.x == 0 && threadIdx.x == 0) g_ctr = GRID_F;
    int idx = blockIdx.x * 256 + threadIdx.x;      // float4 id, total 64K
    float4 v = ((const float4*)cow)[idx];
    float xs[4] = {v.x, v.y, v.z, v.w};
    __nv_bfloat16 hi[4], lo[4];
    #pragma unroll
    for (int i = 0; i < 4; i++) {
        hi[i] = __float2bfloat16(xs[i]);
        lo[i] = __float2bfloat16(xs[i] - __bfloat162float(hi[i]));
    }
    __nv_bfloat162* ph = (__nv_bfloat162*)g_b_hi;
    __nv_bfloat162* pl = (__nv_bfloat162*)g_b_lo;
    ph[idx * 2]     = __nv_bfloat162(hi[0], hi[1]);
    ph[idx * 2 + 1] = __nv_bfloat162(hi[2], hi[3]);
    pl[idx * 2]     = __nv_bfloat162(lo[0], lo[1]);
    pl[idx * 2 + 1] = __nv_bfloat162(lo[2], lo[3]);
}

// ======================= wmma bf16 split GEMM (A split fused in) ===========
#define GA_LD 40
#define GB_LD 136
__global__ void __launch_bounds__(256) gemm_wmma_kernel(
    const float* __restrict__ text, const float* __restrict__ img)
{
    __shared__ __nv_bfloat16 sAhi[64][GA_LD];
    __shared__ __nv_bfloat16 sAlo[64][GA_LD];
    __shared__ __nv_bfloat16 sBhi[32][GB_LD];
    __shared__ __nv_bfloat16 sBlo[32][GB_LD];

    const int tid  = threadIdx.x;
    const int w    = tid >> 5;
    const int wm   = w >> 2;
    const int wn   = w & 3;
    const int row0 = blockIdx.y * 64;
    const int col0 = blockIdx.x * 128;

    wmma::fragment<wmma::accumulator, 16, 16, 16, float> acc[2][2];
    #pragma unroll
    for (int i = 0; i < 2; i++)
        #pragma unroll
        for (int j = 0; j < 2; j++) wmma::fill_fragment(acc[i][j], 0.0f);

    const int aRow = tid >> 2;
    const int aC8  = (tid & 3) * 8;
    const int grow = row0 + aRow;
    const float* srcA = (grow & 1) ? img : text;
    const float* aPtr = srcA + (size_t)(grow >> 1) * D_SZ + aC8;

    for (int kk = 0; kk < D_SZ; kk += 32) {
        float4 av0 = *(const float4*)(aPtr + kk);
        float4 av1 = *(const float4*)(aPtr + kk + 4);
        float xs[8] = {av0.x, av0.y, av0.z, av0.w, av1.x, av1.y, av1.z, av1.w};
        __nv_bfloat16 hi[8], lo[8];
        #pragma unroll
        for (int i = 0; i < 8; i++) {
            hi[i] = __float2bfloat16(xs[i]);
            lo[i] = __float2bfloat16(xs[i] - __bfloat162float(hi[i]));
        }
        *(uint4*)&sAhi[aRow][aC8] = *(const uint4*)hi;
        *(uint4*)&sAlo[aRow][aC8] = *(const uint4*)lo;

        #pragma unroll
        for (int it = 0; it < 2; it++) {
            int s    = tid + it * 256;
            int bRow = s >> 4;
            int bC8  = (s & 15) * 8;
            *(uint4*)&sBhi[bRow][bC8] =
                *(const uint4*)(g_b_hi + (size_t)(kk + bRow) * D_SZ + col0 + bC8);
            *(uint4*)&sBlo[bRow][bC8] =
                *(const uint4*)(g_b_lo + (size_t)(kk + bRow) * D_SZ + col0 + bC8);
        }
        __syncthreads();

        #pragma unroll
        for (int ks = 0; ks < 32; ks += 16) {
            wmma::fragment<wmma::matrix_a, 16, 16, 16, __nv_bfloat16, wmma::row_major> aH[2], aL[2];
            wmma::fragment<wmma::matrix_b, 16, 16, 16, __nv_bfloat16, wmma::row_major> bH[2], bL[2];
            #pragma unroll
            for (int i = 0; i < 2; i++) {
                wmma::load_matrix_sync(aH[i], &sAhi[wm * 32 + i * 16][ks], GA_LD);
                wmma::load_matrix_sync(aL[i], &sAlo[wm * 32 + i * 16][ks], GA_LD);
            }
            #pragma unroll
            for (int j = 0; j < 2; j++) {
                wmma::load_matrix_sync(bH[j], &sBhi[ks][wn * 32 + j * 16], GB_LD);
                wmma::load_matrix_sync(bL[j], &sBlo[ks][wn * 32 + j * 16], GB_LD);
            }
            #pragma unroll
            for (int i = 0; i < 2; i++)
                #pragma unroll
                for (int j = 0; j < 2; j++) {
                    wmma::mma_sync(acc[i][j], aH[i], bH[j], acc[i][j]);
                    wmma::mma_sync(acc[i][j], aH[i], bL[j], acc[i][j]);
                    wmma::mma_sync(acc[i][j], aL[i], bH[j], acc[i][j]);
                }
        }
        __syncthreads();
    }

    #pragma unroll
    for (int i = 0; i < 2; i++)
        #pragma unroll
        for (int j = 0; j < 2; j++)
            wmma::store_matrix_sync(
                g_cw + (size_t)(row0 + wm * 32 + i * 16) * D_SZ + col0 + wn * 32 + j * 16,
                acc[i][j], D_SZ, wmma::mem_row_major);
}

// ======================= fused kernel: R8 body + cp.async z pipeline =======
// dynamic smem layout (floats):
//   cwS   [0, 1024)      ccS [1024, 2048)   wcoS [2048, 2560)  wcaS [2560, 3072)
//   redS  [3072, 5120)   zS  [5120, 13312)  (4 warps x 2 buf x 2 rows x 512)
#define OFF_CW  0
#define OFF_CC  1024
#define OFF_WCO 2048
#define OFF_WCA 2560
#define OFF_RED 3072
#define OFF_Z   5120
#define SMEM_F  13312

__global__ void __launch_bounds__(NT_F, 4) fused_kernel(
    const float* __restrict__ text, const float* __restrict__ img,
    const float* __restrict__ comment, const int* __restrict__ comment_num,
    const float* __restrict__ W_ca, const float* __restrict__ b_ca,
    const float* __restrict__ W_co, const float* __restrict__ b_co,
    float* __restrict__ out)
{
    extern __shared__ float smf[];
    __shared__ float ssumS[4];
    __shared__ float pS[8];
    __shared__ int bS;

    const int tid  = threadIdx.x;
    const int lane = tid & 31;
    const int w    = tid >> 5;

    float* cwS  = smf + OFF_CW;
    float* ccS  = smf + OFF_CC;
    float* wcoS = smf + OFF_WCO;
    float* wcaS = smf + OFF_WCA;
    float* redS = smf + OFF_RED;

    const float4* cw04 = (const float4*)cwS;
    const float4* cw14 = (const float4*)(cwS + D_SZ);
    const float4* c04  = (const float4*)ccS;
    const float4* c14  = (const float4*)(ccS + D_SZ);
    const float4* wco4 = (const float4*)wcoS;

    // this warp's two z buffers (byte addresses for cp.async)
    float* zw0 = smf + OFF_Z + (size_t)(w * 2 + 0) * 2 * D_SZ;  // buf 0: rows 0,1
    float* zw1 = smf + OFF_Z + (size_t)(w * 2 + 1) * 2 * D_SZ;  // buf 1
    const uint32_t zb0 = smem_u32(zw0);
    const uint32_t zb1 = smem_u32(zw1);

    float* out_rcontent = out;
    float* out_rcomment = out + (size_t)B_SZ * D_SZ;
    float* out_contentw = out + (size_t)2 * B_SZ * D_SZ;

    int b = blockIdx.x;
    while (b < B_SZ) {
        const int M = comment_num[b];

        for (int i = tid; i < 2 * D_SZ / 4; i += NT_F)
            ((float4*)cwS)[i] = ((const float4*)(g_cw + (size_t)b * 2 * D_SZ))[i];
        for (int i = tid; i < D_SZ / 4; i += NT_F) {
            ((float4*)ccS)[i]          = ((const float4*)(text + (size_t)b * D_SZ))[i];
            ((float4*)(ccS + D_SZ))[i] = ((const float4*)(img  + (size_t)b * D_SZ))[i];
            ((float4*)wcoS)[i]         = ((const float4*)W_co)[i];
            ((float4*)wcaS)[i]         = ((const float4*)W_ca)[i];
        }
        __syncthreads();

        const float bco = b_co[0];
        const float* zrow = comment + (size_t)b * N_SZ * D_SZ;
        const int npairs = (M + 1) >> 1;

        float4 acc[4], s0[4], s1[4];
        #pragma unroll
        for (int j = 0; j < 4; j++) {
            acc[j] = make_float4(0.f, 0.f, 0.f, 0.f);
            s0[j]  = make_float4(0.f, 0.f, 0.f, 0.f);
            s1[j]  = make_float4(0.f, 0.f, 0.f, 0.f);
        }
        float ssum = 0.f;

        // ---- prologue: async-load pair p=w into buf 0 ----
        if (w < npairs) {
            const int n0 = 2 * w;
            const float* s0g = zrow + (size_t)n0 * D_SZ;
            const int sz1 = (n0 + 1 < M) ? 16 : 0;
            const float* s1g = s0g + (sz1 ? D_SZ : 0);
            #pragma unroll
            for (int j = 0; j < 4; j++) {
                const int o = (lane + 32 * j) * 4;
                cp_async16(zb0 + o * 4,            s0g + o, 16);
                cp_async16(zb0 + (D_SZ + o) * 4,   s1g + o, sz1);
            }
        }
        CP_COMMIT();

        int cur = 0;
        for (int p = w; p < npairs; p += 4) {
            // ---- async-load next pair into the other buffer ----
            const int pn = p + 4;
            const uint32_t znb = cur ? zb0 : zb1;
            if (pn < npairs) {
                const int n0 = 2 * pn;
                const float* s0g = zrow + (size_t)n0 * D_SZ;
                const int sz1 = (n0 + 1 < M) ? 16 : 0;
                const float* s1g = s0g + (sz1 ? D_SZ : 0);
                #pragma unroll
                for (int j = 0; j < 4; j++) {
                    const int o = (lane + 32 * j) * 4;
                    cp_async16(znb + o * 4,          s0g + o, 16);
                    cp_async16(znb + (D_SZ + o) * 4, s1g + o, sz1);
                }
            }
            CP_COMMIT();
            CP_WAIT1();           // current buffer's group complete
            __syncwarp();

            const float* zc = cur ? zw1 : zw0;
            const float4* z0f = (const float4*)zc;
            const float4* z1f = (const float4*)(zc + D_SZ);
            const bool v1 = (2 * p + 1) < M;

            float4 z0[4], z1[4];
            #pragma unroll
            for (int j = 0; j < 4; j++) {
                z0[j] = z0f[lane + 32 * j];
                z1[j] = z1f[lane + 32 * j];
            }

            float a00 = 0.f, a01 = 0.f, a10 = 0.f, a11 = 0.f;
            #pragma unroll
            for (int j = 0; j < 4; j++) {
                float4 ca = cw04[lane + 32 * j];
                float4 cb = cw14[lane + 32 * j];
                a00 = fmaf(z0[j].x, ca.x, fmaf(z0[j].y, ca.y, fmaf(z0[j].z, ca.z, fmaf(z0[j].w, ca.w, a00))));
                a01 = fmaf(z0[j].x, cb.x, fmaf(z0[j].y, cb.y, fmaf(z0[j].z, cb.z, fmaf(z0[j].w, cb.w, a01))));
                a10 = fmaf(z1[j].x, ca.x, fmaf(z1[j].y, ca.y, fmaf(z1[j].z, ca.z, fmaf(z1[j].w, ca.w, a10))));
                a11 = fmaf(z1[j].x, cb.x, fmaf(z1[j].y, cb.y, fmaf(z1[j].z, cb.z, fmaf(z1[j].w, cb.w, a11))));
            }
            a00 = warp_sum(a00); a01 = warp_sum(a01);
            a10 = warp_sum(a10); a11 = warp_sum(a11);
            const float w00 = tanh_precise(a00);
            const float w01 = tanh_precise(a01);
            const float w10 = tanh_precise(a10);
            const float w11 = tanh_precise(a11);

            float l0 = 0.f, l1 = 0.f;
            #pragma unroll
            for (int j = 0; j < 4; j++) {
                float4 u0 = c04[lane + 32 * j];
                float4 u1 = c14[lane + 32 * j];
                float4 wv = wco4[lane + 32 * j];
                l0 = fmaf(tanh_mufu(fmaf(w00, u0.x, fmaf(w01, u1.x, z0[j].x))), wv.x, l0);
                l0 = fmaf(tanh_mufu(fmaf(w00, u0.y, fmaf(w01, u1.y, z0[j].y))), wv.y, l0);
                l0 = fmaf(tanh_mufu(fmaf(w00, u0.z, fmaf(w01, u1.z, z0[j].z))), wv.z, l0);
                l0 = fmaf(tanh_mufu(fmaf(w00, u0.w, fmaf(w01, u1.w, z0[j].w))), wv.w, l0);
                l1 = fmaf(tanh_mufu(fmaf(w10, u0.x, fmaf(w11, u1.x, z1[j].x))), wv.x, l1);
                l1 = fmaf(tanh_mufu(fmaf(w10, u0.y, fmaf(w11, u1.y, z1[j].y))), wv.y, l1);
                l1 = fmaf(tanh_mufu(fmaf(w10, u0.z, fmaf(w11, u1.z, z1[j].z))), wv.z, l1);
                l1 = fmaf(tanh_mufu(fmaf(w10, u0.w, fmaf(w11, u1.w, z1[j].w))), wv.w, l1);
            }
            l0 = warp_sum(l0);
            l1 = warp_sum(l1);

            const float e0 = __expf(l0 + bco);
            const float e1 = v1 ? __expf(l1 + bco) : 0.f;
            ssum += e0 + e1;

            #pragma unroll
            for (int j = 0; j < 4; j++) {
                acc[j].x = fmaf(e0, z0[j].x, fmaf(e1, z1[j].x, acc[j].x));
                acc[j].y = fmaf(e0, z0[j].y, fmaf(e1, z1[j].y, acc[j].y));
                acc[j].z = fmaf(e0, z0[j].z, fmaf(e1, z1[j].z, acc[j].z));
                acc[j].w = fmaf(e0, z0[j].w, fmaf(e1, z1[j].w, acc[j].w));
                s0[j].x  = fmaf(w00, z0[j].x, fmaf(w10, z1[j].x, s0[j].x));
                s0[j].y  = fmaf(w00, z0[j].y, fmaf(w10, z1[j].y, s0[j].y));
                s0[j].z  = fmaf(w00, z0[j].z, fmaf(w10, z1[j].z, s0[j].z));
                s0[j].w  = fmaf(w00, z0[j].w, fmaf(w10, z1[j].w, s0[j].w));
                s1[j].x  = fmaf(w01, z0[j].x, fmaf(w11, z1[j].x, s1[j].x));
                s1[j].y  = fmaf(w01, z0[j].y, fmaf(w11, z1[j].y, s1[j].y));
                s1[j].z  = fmaf(w01, z0[j].z, fmaf(w11, z1[j].z, s1[j].z));
                s1[j].w  = fmaf(w01, z0[j].w, fmaf(w11, z1[j].w, s1[j].w));
            }
            cur ^= 1;
        }
        CP_WAIT0();
        __syncwarp();

        // ---- cross-warp merge: 3 passes through the 8KB redS buffer ----
        float4 A, S0v, S1v;
        {
            #pragma unroll
            for (int j = 0; j < 4; j++)
                ((float4*)redS)[w * 128 + lane + 32 * j] = acc[j];
            if (lane == 0) ssumS[w] = ssum;
            __syncthreads();
            A = make_float4(0.f, 0.f, 0.f, 0.f);
            #pragma unroll
            for (int ww = 0; ww < 4; ww++) {
                float4 a = ((float4*)redS)[ww * 128 + tid];
                A.x += a.x; A.y += a.y; A.z += a.z; A.w += a.w;
            }
            __syncthreads();
            #pragma unroll
            for (int j = 0; j < 4; j++)
                ((float4*)redS)[w * 128 + lane + 32 * j] = s0[j];
            __syncthreads();
            S0v = make_float4(0.f, 0.f, 0.f, 0.f);
            #pragma unroll
            for (int ww = 0; ww < 4; ww++) {
                float4 x = ((float4*)redS)[ww * 128 + tid];
                S0v.x += x.x; S0v.y += x.y; S0v.z += x.z; S0v.w += x.w;
            }
            __syncthreads();
            #pragma unroll
            for (int j = 0; j < 4; j++)
                ((float4*)redS)[w * 128 + lane + 32 * j] = s1[j];
            __syncthreads();
            S1v = make_float4(0.f, 0.f, 0.f, 0.f);
            #pragma unroll
            for (int ww = 0; ww < 4; ww++) {
                float4 y = ((float4*)redS)[ww * 128 + tid];
                S1v.x += y.x; S1v.y += y.y; S1v.z += y.z; S1v.w += y.w;
            }
        }
        const float stot = ssumS[0] + ssumS[1] + ssumS[2] + ssumS[3];
        const float inv = 1.0f / stot;

        ((float4*)out_rcomment)[(size_t)b * 128 + tid] =
            make_float4(A.x * inv, A.y * inv, A.z * inv, A.w * inv);

        float4 c0q = c04[tid], c1q = c14[tid], waq = ((const float4*)wcaS)[tid];
        float p0 = tanh_mufu(c0q.x + S0v.x) * waq.x + tanh_mufu(c0q.y + S0v.y) * waq.y
                 + tanh_mufu(c0q.z + S0v.z) * waq.z + tanh_mufu(c0q.w + S0v.w) * waq.w;
        float p1 = tanh_mufu(c1q.x + S1v.x) * waq.x + tanh_mufu(c1q.y + S1v.y) * waq.y
                 + tanh_mufu(c1q.z + S1v.z) * waq.z + tanh_mufu(c1q.w + S1v.w) * waq.w;
        p0 = warp_sum(p0);
        p1 = warp_sum(p1);
        if (lane == 0) { pS[w] = p0; pS[4 + w] = p1; }
        __syncthreads();
        const float bca = b_ca[0];
        const float l0 = pS[0] + pS[1] + pS[2] + pS[3] + bca;
        const float l1 = pS[4] + pS[5] + pS[6] + pS[7] + bca;

        const float mx = fmaxf(l0, l1);
        const float e0 = __expf(l0 - mx), e1 = __expf(l1 - mx);
        const float is = 1.0f / (e0 + e1);
        const float q0 = e0 * is, q1 = e1 * is;

        if (tid == 0) {
            out_contentw[(size_t)b * 2 + 0] = q0;
            out_contentw[(size_t)b * 2 + 1] = q1;
        }
        ((float4*)out_rcontent)[(size_t)b * 128 + tid] =
            make_float4(c0q.x * q0 + c1q.x * q1, c0q.y * q0 + c1q.y * q1,
                        c0q.z * q0 + c1q.z * q1, c0q.w * q0 + c1q.w * q1);

        // --- fetch next work item (also fences smem reuse) ---
        __syncthreads();
        if (tid == 0) bS = atomicAdd(&g_ctr, 1);
        __syncthreads();
        b = bS;
    }
}

// ---------------------------------------------------------------------------
extern "C" void kernel_launch(void* const* d_in, const int* in_sizes, int n_in,
                              void* d_out, int out_size)
{
    const float* text        = (const float*)d_in[0];
    const float* img         = (const float*)d_in[1];
    const float* comment     = (const float*)d_in[2];
    const int*   comment_num = (const int*)  d_in[3];
    const float* cow         = (const float*)d_in[4];
    const float* W_ca        = (const float*)d_in[5];
    const float* b_ca        = (const float*)d_in[6];
    const float* W_co        = (const float*)d_in[7];
    const float* b_co        = (const float*)d_in[8];
    float* out = (float*)d_out;

    prep_cow_kernel<<<256, 256>>>(cow);

    dim3 gG(D_SZ / 128, (B_SZ * 2) / 64);   // (4, 64)
    gemm_wmma_kernel<<<gG, 256>>>(text, img);

    size_t smem = SMEM_F * sizeof(float);   // 53248 B
    cudaFuncSetAttribute(fused_kernel,
                         cudaFuncAttributeMaxDynamicSharedMemorySize, (int)smem);
    fused_kernel<<<GRID_F, NT_F, smem>>>(text, img, comment, comment_num,
                                         W_ca, b_ca, W_co, b_co, out);
}

// round 13
// speedup vs baseline: 1.1453x; 1.1453x over previous
#include <cuda_runtime.h>
#include <cuda_bf16.h>
#include <mma.h>
#include <cstdint>

#define B_SZ 2048
#define N_SZ 128
#define D_SZ 512
#define NT_F 128
#define GRID_F 592     // 4 CTAs/SM * 148 SMs, persistent

using namespace nvcuda;

// scratch: cw = content @ cow (fp32)
__device__ float g_cw[B_SZ * 2 * D_SZ];                      // 8 MB
__device__ int g_ctr;                                        // work-steal counter

__device__ __forceinline__ float tanh_mufu(float x) {
    float y; asm("tanh.approx.f32 %0, %1;" : "=f"(y) : "f"(x)); return y;
}
__device__ __forceinline__ float tanh_precise(float x) {
    float ax = fabsf(x);
    if (ax > 15.0f) return copysignf(1.0f, x);
    float t = __expf(2.0f * x);
    return (t - 1.0f) / (t + 1.0f);
}
__device__ __forceinline__ float warp_sum(float v) {
    #pragma unroll
    for (int o = 16; o > 0; o >>= 1) v += __shfl_xor_sync(0xffffffffu, v, o);
    return v;
}

// ======================= wmma bf16 split GEMM v2 ===========================
// cw[4096 x 512] = A[4096 x 512] @ B[512 x 512]; 3 split terms (AhBh+AhBl+AlBh).
// BM=128, BN=128, BK=32; 8 warps, warp tile 64x32 (4x2 frags).
// Both A (content) and B (cow) are read as fp32 and hi/lo-split in-register.
#define GA_LD 40
#define GB_LD 136
__global__ void __launch_bounds__(256) gemm_wmma_kernel(
    const float* __restrict__ text, const float* __restrict__ img,
    const float* __restrict__ cow)
{
    if (blockIdx.x == 0 && blockIdx.y == 0 && threadIdx.x == 0) g_ctr = GRID_F;

    __shared__ __nv_bfloat16 sAhi[128][GA_LD];
    __shared__ __nv_bfloat16 sAlo[128][GA_LD];
    __shared__ __nv_bfloat16 sBhi[32][GB_LD];
    __shared__ __nv_bfloat16 sBlo[32][GB_LD];

    const int tid  = threadIdx.x;
    const int w    = tid >> 5;
    const int wm   = w & 1;             // 0..1 (64-row group)
    const int wn   = w >> 1;            // 0..3 (32-col group)
    const int row0 = blockIdx.y * 128;
    const int col0 = blockIdx.x * 128;

    wmma::fragment<wmma::accumulator, 16, 16, 16, float> acc[4][2];
    #pragma unroll
    for (int i = 0; i < 4; i++)
        #pragma unroll
        for (int j = 0; j < 2; j++) wmma::fill_fragment(acc[i][j], 0.0f);

    // A tile: 128x32 fp32, 16 consecutive floats per thread
    const int aRow = tid >> 1;
    const int aC16 = (tid & 1) * 16;
    const int grow = row0 + aRow;
    const float* srcA = (grow & 1) ? img : text;
    const float* aPtr = srcA + (size_t)(grow >> 1) * D_SZ + aC16;
    // B tile: 32x128 fp32, 16 consecutive floats per thread
    const int bRow = tid >> 3;
    const int bC16 = (tid & 7) * 16;

    for (int kk = 0; kk < D_SZ; kk += 32) {
        // ---- A: load fp32, split, store bf16 hi/lo ----
        {
            float xs[16];
            #pragma unroll
            for (int q = 0; q < 4; q++)
                *(float4*)(xs + 4 * q) = *(const float4*)(aPtr + kk + 4 * q);
            __nv_bfloat16 hi[16], lo[16];
            #pragma unroll
            for (int i = 0; i < 16; i++) {
                hi[i] = __float2bfloat16(xs[i]);
                lo[i] = __float2bfloat16(xs[i] - __bfloat162float(hi[i]));
            }
            *(uint4*)&sAhi[aRow][aC16]     = *(const uint4*)(hi);
            *(uint4*)&sAhi[aRow][aC16 + 8] = *(const uint4*)(hi + 8);
            *(uint4*)&sAlo[aRow][aC16]     = *(const uint4*)(lo);
            *(uint4*)&sAlo[aRow][aC16 + 8] = *(const uint4*)(lo + 8);
        }
        // ---- B: load fp32 cow (L2-resident), split, store bf16 hi/lo ----
        {
            const float* bPtr = cow + (size_t)(kk + bRow) * D_SZ + col0 + bC16;
            float xs[16];
            #pragma unroll
            for (int q = 0; q < 4; q++)
                *(float4*)(xs + 4 * q) = *(const float4*)(bPtr + 4 * q);
            __nv_bfloat16 hi[16], lo[16];
            #pragma unroll
            for (int i = 0; i < 16; i++) {
                hi[i] = __float2bfloat16(xs[i]);
                lo[i] = __float2bfloat16(xs[i] - __bfloat162float(hi[i]));
            }
            *(uint4*)&sBhi[bRow][bC16]     = *(const uint4*)(hi);
            *(uint4*)&sBhi[bRow][bC16 + 8] = *(const uint4*)(hi + 8);
            *(uint4*)&sBlo[bRow][bC16]     = *(const uint4*)(lo);
            *(uint4*)&sBlo[bRow][bC16 + 8] = *(const uint4*)(lo + 8);
        }
        __syncthreads();

        #pragma unroll
        for (int ks = 0; ks < 32; ks += 16) {
            wmma::fragment<wmma::matrix_a, 16, 16, 16, __nv_bfloat16, wmma::row_major> aH[4], aL[4];
            wmma::fragment<wmma::matrix_b, 16, 16, 16, __nv_bfloat16, wmma::row_major> bH[2], bL[2];
            #pragma unroll
            for (int i = 0; i < 4; i++) {
                wmma::load_matrix_sync(aH[i], &sAhi[wm * 64 + i * 16][ks], GA_LD);
                wmma::load_matrix_sync(aL[i], &sAlo[wm * 64 + i * 16][ks], GA_LD);
            }
            #pragma unroll
            for (int j = 0; j < 2; j++) {
                wmma::load_matrix_sync(bH[j], &sBhi[ks][wn * 32 + j * 16], GB_LD);
                wmma::load_matrix_sync(bL[j], &sBlo[ks][wn * 32 + j * 16], GB_LD);
            }
            #pragma unroll
            for (int i = 0; i < 4; i++)
                #pragma unroll
                for (int j = 0; j < 2; j++) {
                    wmma::mma_sync(acc[i][j], aH[i], bH[j], acc[i][j]);
                    wmma::mma_sync(acc[i][j], aH[i], bL[j], acc[i][j]);
                    wmma::mma_sync(acc[i][j], aL[i], bH[j], acc[i][j]);
                }
        }
        __syncthreads();
    }

    #pragma unroll
    for (int i = 0; i < 4; i++)
        #pragma unroll
        for (int j = 0; j < 2; j++)
            wmma::store_matrix_sync(
                g_cw + (size_t)(row0 + wm * 64 + i * 16) * D_SZ + col0 + wn * 32 + j * 16,
                acc[i][j], D_SZ, wmma::mem_row_major);
}

// ======================= fused kernel: R8 exact (measured best) ============
__global__ void __launch_bounds__(NT_F, 4) fused_kernel(
    const float* __restrict__ text, const float* __restrict__ img,
    const float* __restrict__ comment, const int* __restrict__ comment_num,
    const float* __restrict__ W_ca, const float* __restrict__ b_ca,
    const float* __restrict__ W_co, const float* __restrict__ b_co,
    float* __restrict__ out)
{
    __shared__ float cwS[2 * D_SZ];
    __shared__ float ccS[2 * D_SZ];
    __shared__ float wcoS[D_SZ];
    __shared__ float wcaS[D_SZ];
    __shared__ float redS[3 * 4 * D_SZ];
    __shared__ float ssumS[4];
    __shared__ float pS[8];
    __shared__ int bS;

    const int tid  = threadIdx.x;
    const int lane = tid & 31;
    const int w    = tid >> 5;

    const float4* cw04 = (const float4*)cwS;
    const float4* cw14 = (const float4*)(cwS + D_SZ);
    const float4* c04  = (const float4*)ccS;
    const float4* c14  = (const float4*)(ccS + D_SZ);
    const float4* wco4 = (const float4*)wcoS;

    float* out_rcontent = out;
    float* out_rcomment = out + (size_t)B_SZ * D_SZ;
    float* out_contentw = out + (size_t)2 * B_SZ * D_SZ;

    int b = blockIdx.x;
    while (b < B_SZ) {
        const int M = comment_num[b];

        for (int i = tid; i < 2 * D_SZ / 4; i += NT_F)
            ((float4*)cwS)[i] = ((const float4*)(g_cw + (size_t)b * 2 * D_SZ))[i];
        for (int i = tid; i < D_SZ / 4; i += NT_F) {
            ((float4*)ccS)[i]          = ((const float4*)(text + (size_t)b * D_SZ))[i];
            ((float4*)(ccS + D_SZ))[i] = ((const float4*)(img  + (size_t)b * D_SZ))[i];
            ((float4*)wcoS)[i]         = ((const float4*)W_co)[i];
            ((float4*)wcaS)[i]         = ((const float4*)W_ca)[i];
        }
        __syncthreads();

        const float bco = b_co[0];

        float4 acc[4], s0[4], s1[4];
        #pragma unroll
        for (int j = 0; j < 4; j++) {
            acc[j] = make_float4(0.f, 0.f, 0.f, 0.f);
            s0[j]  = make_float4(0.f, 0.f, 0.f, 0.f);
            s1[j]  = make_float4(0.f, 0.f, 0.f, 0.f);
        }
        float ssum = 0.f;

        const int npairs = (M + 1) >> 1;
        for (int p = w; p < npairs; p += 4) {
            const int n0 = 2 * p;
            const bool v1 = (n0 + 1) < M;
            const float4* z0p = (const float4*)(comment + ((size_t)b * N_SZ + n0) * D_SZ);
            const float4* z1p = z0p + D_SZ / 4;

            float4 z0[4], z1[4];
            #pragma unroll
            for (int j = 0; j < 4; j++) z0[j] = z0p[lane + 32 * j];
            if (v1) {
                #pragma unroll
                for (int j = 0; j < 4; j++) z1[j] = z1p[lane + 32 * j];
            } else {
                #pragma unroll
                for (int j = 0; j < 4; j++) z1[j] = make_float4(0.f, 0.f, 0.f, 0.f);
            }

            float a00 = 0.f, a01 = 0.f, a10 = 0.f, a11 = 0.f;
            #pragma unroll
            for (int j = 0; j < 4; j++) {
                float4 ca = cw04[lane + 32 * j];
                float4 cb = cw14[lane + 32 * j];
                a00 = fmaf(z0[j].x, ca.x, fmaf(z0[j].y, ca.y, fmaf(z0[j].z, ca.z, fmaf(z0[j].w, ca.w, a00))));
                a01 = fmaf(z0[j].x, cb.x, fmaf(z0[j].y, cb.y, fmaf(z0[j].z, cb.z, fmaf(z0[j].w, cb.w, a01))));
                a10 = fmaf(z1[j].x, ca.x, fmaf(z1[j].y, ca.y, fmaf(z1[j].z, ca.z, fmaf(z1[j].w, ca.w, a10))));
                a11 = fmaf(z1[j].x, cb.x, fmaf(z1[j].y, cb.y, fmaf(z1[j].z, cb.z, fmaf(z1[j].w, cb.w, a11))));
            }
            a00 = warp_sum(a00); a01 = warp_sum(a01);
            a10 = warp_sum(a10); a11 = warp_sum(a11);
            const float w00 = tanh_precise(a00);
            const float w01 = tanh_precise(a01);
            const float w10 = tanh_precise(a10);
            const float w11 = tanh_precise(a11);

            float l0 = 0.f, l1 = 0.f;
            #pragma unroll
            for (int j = 0; j < 4; j++) {
                float4 u0 = c04[lane + 32 * j];
                float4 u1 = c14[lane + 32 * j];
                float4 wv = wco4[lane + 32 * j];
                l0 = fmaf(tanh_mufu(fmaf(w00, u0.x, fmaf(w01, u1.x, z0[j].x))), wv.x, l0);
                l0 = fmaf(tanh_mufu(fmaf(w00, u0.y, fmaf(w01, u1.y, z0[j].y))), wv.y, l0);
                l0 = fmaf(tanh_mufu(fmaf(w00, u0.z, fmaf(w01, u1.z, z0[j].z))), wv.z, l0);
                l0 = fmaf(tanh_mufu(fmaf(w00, u0.w, fmaf(w01, u1.w, z0[j].w))), wv.w, l0);
                l1 = fmaf(tanh_mufu(fmaf(w10, u0.x, fmaf(w11, u1.x, z1[j].x))), wv.x, l1);
                l1 = fmaf(tanh_mufu(fmaf(w10, u0.y, fmaf(w11, u1.y, z1[j].y))), wv.y, l1);
                l1 = fmaf(tanh_mufu(fmaf(w10, u0.z, fmaf(w11, u1.z, z1[j].z))), wv.z, l1);
                l1 = fmaf(tanh_mufu(fmaf(w10, u0.w, fmaf(w11, u1.w, z1[j].w))), wv.w, l1);
            }
            l0 = warp_sum(l0);
            l1 = warp_sum(l1);

            const float e0 = __expf(l0 + bco);
            const float e1 = v1 ? __expf(l1 + bco) : 0.f;
            ssum += e0 + e1;

            #pragma unroll
            for (int j = 0; j < 4; j++) {
                acc[j].x = fmaf(e0, z0[j].x, fmaf(e1, z1[j].x, acc[j].x));
                acc[j].y = fmaf(e0, z0[j].y, fmaf(e1, z1[j].y, acc[j].y));
                acc[j].z = fmaf(e0, z0[j].z, fmaf(e1, z1[j].z, acc[j].z));
                acc[j].w = fmaf(e0, z0[j].w, fmaf(e1, z1[j].w, acc[j].w));
                s0[j].x  = fmaf(w00, z0[j].x, fmaf(w10, z1[j].x, s0[j].x));
                s0[j].y  = fmaf(w00, z0[j].y, fmaf(w10, z1[j].y, s0[j].y));
                s0[j].z  = fmaf(w00, z0[j].z, fmaf(w10, z1[j].z, s0[j].z));
                s0[j].w  = fmaf(w00, z0[j].w, fmaf(w10, z1[j].w, s0[j].w));
                s1[j].x  = fmaf(w01, z0[j].x, fmaf(w11, z1[j].x, s1[j].x));
                s1[j].y  = fmaf(w01, z0[j].y, fmaf(w11, z1[j].y, s1[j].y));
                s1[j].z  = fmaf(w01, z0[j].z, fmaf(w11, z1[j].z, s1[j].z));
                s1[j].w  = fmaf(w01, z0[j].w, fmaf(w11, z1[j].w, s1[j].w));
            }
        }

        #pragma unroll
        for (int j = 0; j < 4; j++) {
            const int idx = w * 128 + lane + 32 * j;
            ((float4*)redS)[idx]        = acc[j];
            ((float4*)redS)[512 + idx]  = s0[j];
            ((float4*)redS)[1024 + idx] = s1[j];
        }
        if (lane == 0) ssumS[w] = ssum;
        __syncthreads();

        float4 A  = make_float4(0.f, 0.f, 0.f, 0.f);
        float4 S0 = make_float4(0.f, 0.f, 0.f, 0.f);
        float4 S1 = make_float4(0.f, 0.f, 0.f, 0.f);
        #pragma unroll
        for (int ww = 0; ww < 4; ww++) {
            float4 a = ((float4*)redS)[ww * 128 + tid];
            float4 x = ((float4*)redS)[512 + ww * 128 + tid];
            float4 y = ((float4*)redS)[1024 + ww * 128 + tid];
            A.x += a.x; A.y += a.y; A.z += a.z; A.w += a.w;
            S0.x += x.x; S0.y += x.y; S0.z += x.z; S0.w += x.w;
            S1.x += y.x; S1.y += y.y; S1.z += y.z; S1.w += y.w;
        }
        const float stot = ssumS[0] + ssumS[1] + ssumS[2] + ssumS[3];
        const float inv = 1.0f / stot;

        ((float4*)out_rcomment)[(size_t)b * 128 + tid] =
            make_float4(A.x * inv, A.y * inv, A.z * inv, A.w * inv);

        float4 c0q = c04[tid], c1q = c14[tid], waq = ((const float4*)wcaS)[tid];
        float p0 = tanh_mufu(c0q.x + S0.x) * waq.x + tanh_mufu(c0q.y + S0.y) * waq.y
                 + tanh_mufu(c0q.z + S0.z) * waq.z + tanh_mufu(c0q.w + S0.w) * waq.w;
        float p1 = tanh_mufu(c1q.x + S1.x) * waq.x + tanh_mufu(c1q.y + S1.y) * waq.y
                 + tanh_mufu(c1q.z + S1.z) * waq.z + tanh_mufu(c1q.w + S1.w) * waq.w;
        p0 = warp_sum(p0);
        p1 = warp_sum(p1);
        if (lane == 0) { pS[w] = p0; pS[4 + w] = p1; }
        __syncthreads();
        const float bca = b_ca[0];
        const float l0 = pS[0] + pS[1] + pS[2] + pS[3] + bca;
        const float l1 = pS[4] + pS[5] + pS[6] + pS[7] + bca;

        const float mx = fmaxf(l0, l1);
        const float e0 = __expf(l0 - mx), e1 = __expf(l1 - mx);
        const float is = 1.0f / (e0 + e1);
        const float q0 = e0 * is, q1 = e1 * is;

        if (tid == 0) {
            out_contentw[(size_t)b * 2 + 0] = q0;
            out_contentw[(size_t)b * 2 + 1] = q1;
        }
        ((float4*)out_rcontent)[(size_t)b * 128 + tid] =
            make_float4(c0q.x * q0 + c1q.x * q1, c0q.y * q0 + c1q.y * q1,
                        c0q.z * q0 + c1q.z * q1, c0q.w * q0 + c1q.w * q1);

        // --- fetch next work item (also fences smem reuse) ---
        __syncthreads();
        if (tid == 0) bS = atomicAdd(&g_ctr, 1);
        __syncthreads();
        b = bS;
    }
}

// ---------------------------------------------------------------------------
extern "C" void kernel_launch(void* const* d_in, const int* in_sizes, int n_in,
                              void* d_out, int out_size)
{
    const float* text        = (const float*)d_in[0];
    const float* img         = (const float*)d_in[1];
    const float* comment     = (const float*)d_in[2];
    const int*   comment_num = (const int*)  d_in[3];
    const float* cow         = (const float*)d_in[4];
    const float* W_ca        = (const float*)d_in[5];
    const float* b_ca        = (const float*)d_in[6];
    const float* W_co        = (const float*)d_in[7];
    const float* b_co        = (const float*)d_in[8];
    float* out = (float*)d_out;

    dim3 gG(D_SZ / 128, (B_SZ * 2) / 128);   // (4, 32)
    gemm_wmma_kernel<<<gG, 256>>>(text, img, cow);

    fused_kernel<<<GRID_F, NT_F>>>(text, img, comment, comment_num,
                                   W_ca, b_ca, W_co, b_co, out);
}